// round 10
// baseline (speedup 1.0000x reference)
#include <cuda_runtime.h>
#include <cuda_bf16.h>
#include <cstdint>

#define TT 25
#define BB 4096
#define INP 500
#define HH 64
#define GG 256   // 4*H
#define NL 25
#define NTHR 256

typedef unsigned long long ull;

// scratch (sanctioned: __device__ globals)
// g_xp0 packed-pair layout: [row][p*32+lane] = (gate lane+64p, gate lane+64p+32)
__device__ ull   g_xp0[(size_t)TT * BB * 128];
__device__ float g_hs[2][(size_t)TT * BB * HH];

// ---------------- scalar helpers ----------------
__device__ __forceinline__ ull ffma2(ull a, ull b, ull c) {
    ull d; asm("fma.rn.f32x2 %0, %1, %2, %3;" : "=l"(d) : "l"(a), "l"(b), "l"(c)); return d;
}
__device__ __forceinline__ ull pack2(float x, float y) {
    ull d; asm("mov.b64 %0, {%1, %2};" : "=l"(d) : "f"(x), "f"(y)); return d;
}
__device__ __forceinline__ float2 unpack2(ull v) {
    float2 r; asm("mov.b64 {%0, %1}, %2;" : "=f"(r.x), "=f"(r.y) : "l"(v)); return r;
}
__device__ __forceinline__ float sigf(float x) {
    return __fdividef(1.0f, 1.0f + __expf(-x));
}
__device__ __forceinline__ float tanhf_fast(float x) {
    return 1.0f - __fdividef(2.0f, __expf(2.0f * x) + 1.0f);
}
__device__ __forceinline__ void mma16816(float* c, const uint32_t* a, uint32_t b0, uint32_t b1) {
    asm volatile(
        "mma.sync.aligned.m16n8k16.row.col.f32.bf16.bf16.f32 "
        "{%0,%1,%2,%3}, {%4,%5,%6,%7}, {%8,%9}, {%0,%1,%2,%3};"
        : "+f"(c[0]), "+f"(c[1]), "+f"(c[2]), "+f"(c[3])
        : "r"(a[0]), "r"(a[1]), "r"(a[2]), "r"(a[3]), "r"(b0), "r"(b1));
}

// shared weight layout (ull): slot [(k*4+p)*32 + lane] = (W[lane+64p][k], W[lane+64p+32][k])

// ---------------------------------------------------------------------------
// Layer-0 input projection (K=500, fp32 SIMT) -> g_xp0 packed pairs, bias folded
// ---------------------------------------------------------------------------
#define RPP 64
__global__ void __launch_bounds__(NTHR)
proj0_kernel(const float* __restrict__ x, const float* __restrict__ W,
             const float* __restrict__ bih, const float* __restrict__ bhh)
{
    extern __shared__ unsigned char smraw[];
    ull*   shW     = (ull*)smraw;                        // 64*4*32 ull = 64 KB
    float* scratch = (float*)(smraw + 65536);            // [256][65]
    float* shX     = (float*)(smraw + 65536 + 66560);    // [64][64]
    const int tid = threadIdx.x, lane = tid & 31, w = tid >> 5;
    const int rowBase = blockIdx.x * RPP;

    ull acc[8][4];
#pragma unroll
    for (int p = 0; p < 4; ++p) {
        int g0 = lane + 64 * p, g1 = g0 + 32;
        ull b = pack2(bih[g0] + bhh[g0], bih[g1] + bhh[g1]);
#pragma unroll
        for (int r = 0; r < 8; ++r) acc[r][p] = b;
    }

    for (int k0 = 0; k0 < INP; k0 += 64) {
        for (int idx = tid; idx < 64 * GG; idx += NTHR) {
            int kk = idx & 63, g = idx >> 6;
            scratch[g * 65 + kk] = (k0 + kk < INP) ? W[(size_t)g * INP + k0 + kk] : 0.0f;
        }
        for (int idx = tid; idx < RPP * 64; idx += NTHR) {
            int kk = idx & 63, r = idx >> 6;
            shX[r * 64 + kk] = (k0 + kk < INP) ? x[(size_t)(rowBase + r) * INP + k0 + kk] : 0.0f;
        }
        __syncthreads();
        for (int idx = tid; idx < 64 * 128; idx += NTHR) {
            int l2 = idx & 31, p = (idx >> 5) & 3, kk = idx >> 7;
            int g0 = 64 * p + l2;
            shW[(kk * 4 + p) * 32 + l2] = pack2(scratch[g0 * 65 + kk], scratch[(g0 + 32) * 65 + kk]);
        }
        __syncthreads();
#pragma unroll 2
        for (int k4 = 0; k4 < 64; k4 += 4) {
            float4 xq[8];
#pragma unroll
            for (int r = 0; r < 8; ++r) xq[r] = *(const float4*)&shX[(8 * w + r) * 64 + k4];
#pragma unroll
            for (int kk = 0; kk < 4; ++kk) {
                ull wv[4];
#pragma unroll
                for (int p = 0; p < 4; ++p) wv[p] = shW[((k4 + kk) * 4 + p) * 32 + lane];
#pragma unroll
                for (int r = 0; r < 8; ++r) {
                    float xv = ((const float*)&xq[r])[kk];
                    ull xx = pack2(xv, xv);
#pragma unroll
                    for (int p = 0; p < 4; ++p) acc[r][p] = ffma2(xx, wv[p], acc[r][p]);
                }
            }
        }
        __syncthreads();
    }
#pragma unroll
    for (int r = 0; r < 8; ++r) {
        size_t rb = (size_t)(rowBase + 8 * w + r) * 128;
#pragma unroll
        for (int p = 0; p < 4; ++p) g_xp0[rb + p * 32 + lane] = acc[r][p];
    }
}

// ---------------------------------------------------------------------------
// xproj_kernel: HMMA (mma.sync bf16) GEMM
//   xp[row][g] = sum_k hs_in[row][k]*Wih[g][k] + bih[g]+bhh[g]
// 3-term split-bf16, K-concat 192: [A_hi|A_lo|A_hi] x [B_hi|B_hi|B_lo].
// CTA: 512 thr / 16 warps; 128 rows x 256 gates; warp tile 32x64. grid 800.
// smem: A bf16[128][200] @1024 | B bf16[256][200] @52224 | bias f32[256] @154624
//       C f32[128][264] overlays A/B after compute.
// ---------------------------------------------------------------------------
#define XSA 200
#define XSB 200
#define XCS 264
#define XA 1024
#define XB (XA + 128 * XSA * 2)          // 52224
#define XBIAS (XB + 256 * XSB * 2)       // 154624
#define XTOT (XBIAS + 1024)              // 155648

__global__ void __launch_bounds__(512)
xproj_kernel(int inSel, const float* __restrict__ Wih,
             const float* __restrict__ bih, const float* __restrict__ bhh)
{
    extern __shared__ unsigned char sm[];
    __nv_bfloat16* As = (__nv_bfloat16*)(sm + XA);
    __nv_bfloat16* Bs = (__nv_bfloat16*)(sm + XB);
    float* Cs   = (float*)(sm + XA);
    float* bias = (float*)(sm + XBIAS);
    const int tid = threadIdx.x, lane = tid & 31, w = tid >> 5;
    const int grp = lane >> 2, tg = lane & 3;
    const size_t rowBase = (size_t)blockIdx.x * 128;
    const float* __restrict__ hs_in = g_hs[inSel];

    // stage A (hs rows) split hi/lo
    for (int idx = tid; idx < 128 * 64; idx += 512) {
        int r = idx >> 6, k = idx & 63;
        float v = hs_in[(rowBase + r) * HH + k];
        __nv_bfloat16 hi = __float2bfloat16(v);
        __nv_bfloat16 lo = __float2bfloat16(v - __bfloat162float(hi));
        As[r * XSA + k]       = hi;
        As[r * XSA + 64 + k]  = lo;
        As[r * XSA + 128 + k] = hi;
    }
    // stage B (weights) split hi/lo
    for (int idx = tid; idx < 256 * 64; idx += 512) {
        int g = idx >> 6, k = idx & 63;
        float v = Wih[g * HH + k];
        __nv_bfloat16 hi = __float2bfloat16(v);
        __nv_bfloat16 lo = __float2bfloat16(v - __bfloat162float(hi));
        Bs[g * XSB + k]       = hi;
        Bs[g * XSB + 64 + k]  = hi;
        Bs[g * XSB + 128 + k] = lo;
    }
    if (tid < 256) bias[tid] = bih[tid] + bhh[tid];
    __syncthreads();

    // warp tile: rows mrow..mrow+31, gates ncol..ncol+63
    const int mrow = (w & 3) * 32;
    const int ncol = (w >> 2) * 64;

    float acc[2][8][4];
#pragma unroll
    for (int mt = 0; mt < 2; ++mt)
#pragma unroll
        for (int nt = 0; nt < 8; ++nt)
#pragma unroll
            for (int q = 0; q < 4; ++q) acc[mt][nt][q] = 0.0f;

#pragma unroll
    for (int ks = 0; ks < 12; ++ks) {
        const int k0 = ks * 16;
        uint32_t af[2][4];
#pragma unroll
        for (int mt = 0; mt < 2; ++mt) {
            int row = mrow + mt * 16 + grp;
            af[mt][0] = *(const uint32_t*)&As[row * XSA + k0 + tg * 2];
            af[mt][1] = *(const uint32_t*)&As[(row + 8) * XSA + k0 + tg * 2];
            af[mt][2] = *(const uint32_t*)&As[row * XSA + k0 + tg * 2 + 8];
            af[mt][3] = *(const uint32_t*)&As[(row + 8) * XSA + k0 + tg * 2 + 8];
        }
#pragma unroll
        for (int nt = 0; nt < 8; ++nt) {
            int col = ncol + nt * 8 + grp;
            uint32_t b0 = *(const uint32_t*)&Bs[col * XSB + k0 + tg * 2];
            uint32_t b1 = *(const uint32_t*)&Bs[col * XSB + k0 + tg * 2 + 8];
            mma16816(acc[0][nt], af[0], b0, b1);
            mma16816(acc[1][nt], af[1], b0, b1);
        }
    }
    __syncthreads();   // all warps done reading As/Bs; Cs overlays them

    // store C fragments to smem
#pragma unroll
    for (int mt = 0; mt < 2; ++mt) {
        int row = mrow + mt * 16 + grp;
#pragma unroll
        for (int nt = 0; nt < 8; ++nt) {
            int col = ncol + nt * 8 + tg * 2;
            *(float2*)&Cs[row * XCS + col]       = make_float2(acc[mt][nt][0], acc[mt][nt][1]);
            *(float2*)&Cs[(row + 8) * XCS + col] = make_float2(acc[mt][nt][2], acc[mt][nt][3]);
        }
    }
    __syncthreads();

    // repack to g_xp0 packed-pair ull layout, bias folded
    for (int idx = tid; idx < 128 * 128; idx += 512) {
        int row = idx >> 7, q = idx & 127;
        int p = q >> 5, l2 = q & 31;
        int g0 = 64 * p + l2, g1 = g0 + 32;
        g_xp0[(rowBase + row) * 128 + q] =
            pack2(Cs[row * XCS + g0] + bias[g0], Cs[row * XCS + g1] + bias[g1]);
    }
}

// ---------------------------------------------------------------------------
// Recurrence (K=64): gates = xp0[t] + h @ Whh^T. 32 rows/block, all layers.
// ---------------------------------------------------------------------------
__global__ void __launch_bounds__(NTHR)
rec_kernel(const float* __restrict__ Whh, int outSel,
           float* __restrict__ out_hn, float* __restrict__ out_cn)
{
    extern __shared__ unsigned char smraw[];
    ull*   shW  = (ull*)smraw;                 // 64*4*32 ull
    float* shWf = (float*)shW;
    float* shH  = (float*)(smraw + 65536);     // [32][64]
    const int tid = threadIdx.x, lane = tid & 31, w = tid >> 5;
    const int rowBase = blockIdx.x * 32;
    float* __restrict__ hs_out = g_hs[outSel];

    for (int idx = tid; idx < 64 * GG; idx += NTHR) {
        int g = idx & 255, kk = idx >> 8;
        int p = g >> 6, half = (g >> 5) & 1, l2 = g & 31;
        shWf[((kk * 4 + p) * 32 + l2) * 2 + half] = Whh[g * HH + kk];
    }
    for (int idx = tid; idx < 32 * HH; idx += NTHR) shH[idx] = 0.0f;
    __syncthreads();

    float c0[4] = {0, 0, 0, 0}, c1[4] = {0, 0, 0, 0};

    for (int t = 0; t < TT; ++t) {
        ull acc[4][4];
#pragma unroll
        for (int r = 0; r < 4; ++r) {
            size_t base = ((size_t)t * BB + rowBase + 4 * w + r) * 128;
#pragma unroll
            for (int p = 0; p < 4; ++p) acc[r][p] = g_xp0[base + p * 32 + lane];
        }
#pragma unroll 4
        for (int k4 = 0; k4 < 64; k4 += 4) {
            float4 xq[4];
#pragma unroll
            for (int r = 0; r < 4; ++r) xq[r] = *(const float4*)&shH[(4 * w + r) * 64 + k4];
#pragma unroll
            for (int kk = 0; kk < 4; ++kk) {
                ull wv[4];
#pragma unroll
                for (int p = 0; p < 4; ++p) wv[p] = shW[((k4 + kk) * 4 + p) * 32 + lane];
#pragma unroll
                for (int r = 0; r < 4; ++r) {
                    float xv = ((const float*)&xq[r])[kk];
                    ull xx = pack2(xv, xv);
#pragma unroll
                    for (int p = 0; p < 4; ++p) acc[r][p] = ffma2(xx, wv[p], acc[r][p]);
                }
            }
        }
        __syncwarp();
#pragma unroll
        for (int r = 0; r < 4; ++r) {
            float2 fi = unpack2(acc[r][0]), ff = unpack2(acc[r][1]);
            float2 fq = unpack2(acc[r][2]), fo = unpack2(acc[r][3]);
            float i0 = sigf(fi.x), i1 = sigf(fi.y);
            float f0 = sigf(ff.x), f1 = sigf(ff.y);
            float q0 = tanhf_fast(fq.x), q1 = tanhf_fast(fq.y);
            float o0 = sigf(fo.x), o1 = sigf(fo.y);
            c0[r] = f0 * c0[r] + i0 * q0;
            c1[r] = f1 * c1[r] + i1 * q1;
            float h0 = o0 * tanhf_fast(c0[r]);
            float h1 = o1 * tanhf_fast(c1[r]);
            shH[(4 * w + r) * 64 + lane]      = h0;
            shH[(4 * w + r) * 64 + lane + 32] = h1;
            size_t ob = ((size_t)t * BB + rowBase + 4 * w + r) * HH;
            hs_out[ob + lane]      = h0;
            hs_out[ob + lane + 32] = h1;
            if (t == TT - 1) {
                size_t hb = (size_t)(rowBase + 4 * w + r) * HH;
                out_hn[hb + lane] = h0;      out_hn[hb + lane + 32] = h1;
                out_cn[hb + lane] = c0[r];   out_cn[hb + lane + 32] = c1[r];
            }
        }
        __syncwarp();
    }
}

// ---------------------------------------------------------------------------
// Final linear on hs[:, -1, :] (batch index B-1, faithful to reference quirk)
// ---------------------------------------------------------------------------
__global__ void final_kernel(const float* __restrict__ Wlin,
                             const float* __restrict__ blin,
                             float* __restrict__ out)
{
    int idx = threadIdx.x;
    if (idx < TT * 10) {
        int t = idx / 10, o = idx % 10;
        const float* h = &g_hs[0][((size_t)t * BB + (BB - 1)) * HH];
        float s = blin[o];
#pragma unroll
        for (int k = 0; k < HH; ++k) s += h[k] * Wlin[o * HH + k];
        out[idx] = s;
    }
}

// ---------------------------------------------------------------------------
extern "C" void kernel_launch(void* const* d_in, const int* in_sizes, int n_in,
                              void* d_out, int out_size)
{
    const float* x    = (const float*)d_in[0];
    const float* Wih0 = (const float*)d_in[1];
    const float* Whh0 = (const float*)d_in[2];
    const float* bih0 = (const float*)d_in[3];
    const float* bhh0 = (const float*)d_in[4];
    const float* WihR = (const float*)d_in[5];
    const float* WhhR = (const float*)d_in[6];
    const float* bihR = (const float*)d_in[7];
    const float* bhhR = (const float*)d_in[8];
    const float* Wlin = (const float*)d_in[9];
    const float* blin = (const float*)d_in[10];

    float* out = (float*)d_out;
    float* hn  = out + TT * 10;
    float* cn  = hn + (size_t)NL * BB * HH;

    const int SH_P = 65536 + 66560 + RPP * 64 * 4;   // 148480 B
    const int SH_R = 65536 + 32 * 64 * 4;            // 73728 B

    cudaFuncSetAttribute(proj0_kernel, cudaFuncAttributeMaxDynamicSharedMemorySize, SH_P);
    cudaFuncSetAttribute(rec_kernel,   cudaFuncAttributeMaxDynamicSharedMemorySize, SH_R);
    cudaFuncSetAttribute(xproj_kernel, cudaFuncAttributeMaxDynamicSharedMemorySize, XTOT);

    proj0_kernel<<<(TT * BB) / RPP, NTHR, SH_P>>>(x, Wih0, bih0, bhh0);
    rec_kernel<<<BB / 32, NTHR, SH_R>>>(Whh0, 0, hn, cn);

    for (int l = 1; l < NL; ++l) {
        int lr = l - 1;
        xproj_kernel<<<(TT * BB) / 128, 512, XTOT>>>(
            (l - 1) & 1, WihR + (size_t)lr * GG * HH, bihR + lr * GG, bhhR + lr * GG);
        rec_kernel<<<BB / 32, NTHR, SH_R>>>(
            WhhR + (size_t)lr * GG * HH, l & 1,
            hn + (size_t)l * BB * HH, cn + (size_t)l * BB * HH);
    }

    final_kernel<<<1, 256>>>(Wlin, blin, out);
}